// round 12
// baseline (speedup 1.0000x reference)
#include <cuda_runtime.h>
#include <math.h>
#include <stdint.h>

#define BATCH   32
#define TLEN    2048
#define HE      1024
#define NCHUNK  9                 // 288 CTAs = one full wave at occ 2 (148 SMs)
#define CBASE   (TLEN / NCHUNK)   // 227
#define CREM    (TLEN - CBASE * NCHUNK) // 5 chunks get one extra row
#define THREADS 256
#define WARPS   (THREADS / 32)

// Cross-CTA partials (allocation-free scratch)
__device__ float g_pz[BATCH * NCHUNK];
__device__ float g_pacc[BATCH * NCHUNK * HE];
__device__ unsigned int g_ticket[BATCH];   // zero-init; self-resetting

__global__ __launch_bounds__(THREADS, 2)
void attn_fused_kernel(const float* __restrict__ hidden,   // (2,32,1024)
                       const float* __restrict__ enc,      // (32,2048,1024)
                       const float* __restrict__ mask,     // (32,2048)
                       const float* __restrict__ attn_w,   // (3072,)
                       const float* __restrict__ attn_b,   // (1,)
                       float* __restrict__ out)            // (32,1024)
{
    __shared__ float s_we[HE];             // w_e staged in smem
    __shared__ float s_acc[WARPS * HE];    // 32KB warp-partial reduce
    __shared__ float s_z[WARPS];
    __shared__ float s_red[WARPS];
    __shared__ float s_hb;
    __shared__ unsigned s_ticket;

    const int tid   = threadIdx.x;
    const int lane  = tid & 31;
    const int warp  = tid >> 5;
    const int b     = blockIdx.x / NCHUNK;
    const int chunk = blockIdx.x % NCHUNK;

    const int t_begin = chunk * CBASE + min(chunk, CREM);
    const int t_end   = t_begin + CBASE + (chunk < CREM ? 1 : 0);

    // ---- stage w_e into smem ----
    for (int i = tid; i < HE; i += THREADS) s_we[i] = attn_w[2048 + i];

    // ---- hb = hid_flat[b].w_h + bias ----
    float hsum = 0.f;
    for (int i = tid; i < 2048; i += THREADS) {
        int j = i >> 10, k = i & 1023;
        hsum += hidden[(size_t)j * BATCH * HE + (size_t)b * HE + k] * attn_w[i];
    }
    #pragma unroll
    for (int o = 16; o; o >>= 1) hsum += __shfl_xor_sync(0xffffffffu, hsum, o);
    if (lane == 0) s_red[warp] = hsum;
    __syncthreads();
    if (tid == 0) {
        float s = 0.f;
        #pragma unroll
        for (int w = 0; w < WARPS; w++) s += s_red[w];
        s_hb = s + attn_b[0];
    }
    __syncthreads();
    const float hb = s_hb;

    const float*  mrow = mask + (size_t)b * TLEN;
    const float4* encb = (const float4*)(enc + (size_t)b * TLEN * HE);
    const float4* wsm  = (const float4*)s_we;

    float z = 0.f;
    float4 acc[8];
    #pragma unroll
    for (int i = 0; i < 8; i++) acc[i] = make_float4(0.f, 0.f, 0.f, 0.f);

    // ---- mainloop: 2 rows per warp-iteration, reduces interleaved ----
    int t = t_begin + warp;
    for (; t + WARPS < t_end; t += 2 * WARPS) {
        const int t2 = t + WARPS;
        const float4* r0 = encb + (size_t)t  * (HE / 4);
        const float4* r1 = encb + (size_t)t2 * (HE / 4);

        float4 va[8], vb[8];
        #pragma unroll
        for (int i = 0; i < 8; i++) va[i] = r0[lane + 32 * i];   // 16 LDG.128
        #pragma unroll
        for (int i = 0; i < 8; i++) vb[i] = r1[lane + 32 * i];   // all in flight

        float e0 = 0.f, e1 = 0.f;
        #pragma unroll
        for (int i = 0; i < 8; i++) {
            float4 w = wsm[lane + 32 * i];
            e0 += va[i].x * w.x + va[i].y * w.y + va[i].z * w.z + va[i].w * w.w;
            e1 += vb[i].x * w.x + vb[i].y * w.y + vb[i].z * w.z + vb[i].w * w.w;
        }
        #pragma unroll
        for (int o = 16; o; o >>= 1) {                // two chains interleaved (ILP-2)
            e0 += __shfl_xor_sync(0xffffffffu, e0, o);
            e1 += __shfl_xor_sync(0xffffffffu, e1, o);
        }

        const float mk0 = mrow[t], mk1 = mrow[t2];
        // energies*mask before softmax; exp without max (|e|~O(6)); *mask after
        const float w0 = __expf((e0 + hb) * mk0) * mk0;
        const float w1 = __expf((e1 + hb) * mk1) * mk1;
        z += w0 + w1;
        #pragma unroll
        for (int i = 0; i < 8; i++) {
            acc[i].x += w0 * va[i].x + w1 * vb[i].x;
            acc[i].y += w0 * va[i].y + w1 * vb[i].y;
            acc[i].z += w0 * va[i].z + w1 * vb[i].z;
            acc[i].w += w0 * va[i].w + w1 * vb[i].w;
        }
    }
    // ---- tail: at most one leftover row per warp ----
    if (t < t_end) {
        const float4* r0 = encb + (size_t)t * (HE / 4);
        float4 va[8];
        #pragma unroll
        for (int i = 0; i < 8; i++) va[i] = r0[lane + 32 * i];
        float e0 = 0.f;
        #pragma unroll
        for (int i = 0; i < 8; i++) {
            float4 w = wsm[lane + 32 * i];
            e0 += va[i].x * w.x + va[i].y * w.y + va[i].z * w.z + va[i].w * w.w;
        }
        #pragma unroll
        for (int o = 16; o; o >>= 1) e0 += __shfl_xor_sync(0xffffffffu, e0, o);
        const float mk0 = mrow[t];
        const float w0 = __expf((e0 + hb) * mk0) * mk0;
        z += w0;
        #pragma unroll
        for (int i = 0; i < 8; i++) {
            acc[i].x += w0 * va[i].x; acc[i].y += w0 * va[i].y;
            acc[i].z += w0 * va[i].z; acc[i].w += w0 * va[i].w;
        }
    }

    // ---- CTA reduction of 8 warp partials ----
    #pragma unroll
    for (int i = 0; i < 8; i++)
        ((float4*)s_acc)[warp * (HE / 4) + i * 32 + lane] = acc[i];
    if (lane == 0) s_z[warp] = z;
    __syncthreads();

    float4 o = make_float4(0.f, 0.f, 0.f, 0.f);
    #pragma unroll
    for (int w = 0; w < WARPS; w++) {
        float4 a = ((const float4*)s_acc)[w * (HE / 4) + tid];
        o.x += a.x; o.y += a.y; o.z += a.z; o.w += a.w;
    }
    float zc = 0.f;
    if (tid == 0) {
        #pragma unroll
        for (int w = 0; w < WARPS; w++) zc += s_z[w];
    }

    // ---- write partials; ticketed last-CTA combine per batch ----
    const int pidx = b * NCHUNK + chunk;
    if (tid == 0) g_pz[pidx] = zc;
    ((float4*)(g_pacc + (size_t)pidx * HE))[tid] = o;
    __threadfence();
    __syncthreads();
    if (tid == 0) s_ticket = atomicAdd(&g_ticket[b], 1u);
    __syncthreads();

    if (s_ticket == NCHUNK - 1) {
        __threadfence();   // acquire peer partials

        float Z = 0.f;
        #pragma unroll
        for (int c = 0; c < NCHUNK; c++) Z += g_pz[b * NCHUNK + c];
        const float inv = 1.f / Z;

        float4 r = make_float4(0.f, 0.f, 0.f, 0.f);
        #pragma unroll
        for (int c = 0; c < NCHUNK; c++) {
            float4 a = ((const float4*)(g_pacc + (size_t)(b * NCHUNK + c) * HE))[tid];
            r.x += a.x; r.y += a.y; r.z += a.z; r.w += a.w;
        }
        r.x *= inv; r.y *= inv; r.z *= inv; r.w *= inv;
        ((float4*)(out + (size_t)b * HE))[tid] = r;

        if (tid == 0) g_ticket[b] = 0;   // self-reset for next graph replay
    }
}

extern "C" void kernel_launch(void* const* d_in, const int* in_sizes, int n_in,
                              void* d_out, int out_size)
{
    const float* hidden = (const float*)d_in[0];  // (2,32,1024)
    const float* enc    = (const float*)d_in[1];  // (32,2048,1024)
    const float* mask   = (const float*)d_in[2];  // (32,2048)
    const float* attn_w = (const float*)d_in[3];  // (3072,)
    const float* attn_b = (const float*)d_in[4];  // (1,)
    float* out = (float*)d_out;                   // (32,1024)

    attn_fused_kernel<<<BATCH * NCHUNK, THREADS>>>(
        hidden, enc, mask, attn_w, attn_b, out);
}